// round 3
// baseline (speedup 1.0000x reference)
#include <cuda_runtime.h>
#include <cuda_bf16.h>

// SingleRoIExtractor: FPN RoIAlign (aligned=False), out 7x7, sr=2.
// R2: one thread per (bin, sample) per RoI; geometry computed once in regs,
// channel loop is pure LDG+FFMA; 4-lane shfl reduce; streaming stores.

#define OUTS   7
#define CH     256
#define BINS   (OUTS * OUTS)          // 49
#define PER_ROI (CH * BINS)           // 12544
#define NSAMP  4                      // sr*sr
#define ACTIVE (BINS * NSAMP)         // 196
#define BLK    224                    // 7 warps; threads >= 196 idle

__global__ void __launch_bounds__(BLK)
roi_extract_kernel(const float* __restrict__ f0,
                   const float* __restrict__ f1,
                   const float* __restrict__ f2,
                   const float* __restrict__ f3,
                   const float* __restrict__ rois,
                   float* __restrict__ out)
{
    const int t = threadIdx.x;
    if (t >= ACTIVE) return;

    const int n   = blockIdx.x;
    const int bin = t >> 2;           // 0..48
    const int s   = t & 3;            // sample id: iy = s>>1, ix = s&1
    const int ph  = bin / OUTS;
    const int pw  = bin - ph * OUTS;
    const int iy  = s >> 1;
    const int ix  = s & 1;

    // ---- per-RoI params (computed redundantly per thread; once per 256-ch loop) ----
    const float rb  = __ldg(rois + n * 5 + 0);
    const float rx1 = __ldg(rois + n * 5 + 1);
    const float ry1 = __ldg(rois + n * 5 + 2);
    const float rx2 = __ldg(rois + n * 5 + 3);
    const float ry2 = __ldg(rois + n * 5 + 4);

    const float sc = sqrtf((rx2 - rx1 + 1.0f) * (ry2 - ry1 + 1.0f));
    int lvl = (int)floorf(log2f(sc * (1.0f / 56.0f) + 1e-6f));
    lvl = lvl < 0 ? 0 : (lvl > 3 ? 3 : lvl);

    const float* f; int H, W; float ss;
    if      (lvl == 0) { f = f0; H = 200; W = 304; ss = 0.25f;    }
    else if (lvl == 1) { f = f1; H = 100; W = 152; ss = 0.125f;   }
    else if (lvl == 2) { f = f2; H = 50;  W = 76;  ss = 0.0625f;  }
    else               { f = f3; H = 25;  W = 38;  ss = 0.03125f; }

    const int   b  = (int)rb;
    const int   HW = H * W;
    const float x1 = rx1 * ss, y1 = ry1 * ss;
    const float rw = fmaxf(rx2 * ss - x1, 1.0f);
    const float rh = fmaxf(ry2 * ss - y1, 1.0f);
    const float binw = rw * (1.0f / OUTS);
    const float binh = rh * (1.0f / OUTS);

    // ---- sample geometry (once, in registers) ----
    const float Hf = (float)H, Wf = (float)W;
    const float y = y1 + ((float)(ph * 2 + iy) + 0.5f) * 0.5f * binh;
    const float x = x1 + ((float)(pw * 2 + ix) + 0.5f) * 0.5f * binw;
    const bool valid = (y >= -1.0f) & (y <= Hf) & (x >= -1.0f) & (x <= Wf);

    const float yc = fminf(fmaxf(y, 0.0f), Hf - 1.0f);
    const float xc = fminf(fmaxf(x, 0.0f), Wf - 1.0f);
    const int   y0 = (int)yc;
    const int   x0 = (int)xc;
    const float ly = yc - (float)y0;
    const float lx = xc - (float)x0;
    const int   yB = min(y0 + 1, H - 1);
    const int   xB = min(x0 + 1, W - 1);

    const float vmul = valid ? 1.0f : 0.0f;
    const float wy0 = (1.0f - ly) * vmul;
    const float wy1 = ly * vmul;
    const float w00 = wy0 * (1.0f - lx);
    const float w01 = wy0 * lx;
    const float w10 = wy1 * (1.0f - lx);
    const float w11 = wy1 * lx;

    const int o00 = y0 * W + x0;
    const int o01 = y0 * W + xB;
    const int o10 = yB * W + x0;
    const int o11 = yB * W + xB;

    const float* __restrict__ p = f + (size_t)b * CH * HW;
    float* __restrict__ po = out + (size_t)n * PER_ROI + bin;

    // shfl group: 4 consecutive lanes
    const int lane = t & 31;
    const unsigned gmask = 0xFu << (lane & ~3);

    #pragma unroll 4
    for (int c = 0; c < CH; ++c) {
        float v = __ldg(p + o00) * w00
                + __ldg(p + o01) * w01
                + __ldg(p + o10) * w10
                + __ldg(p + o11) * w11;
        // reduce 4 samples -> lane s==0 of each group
        v += __shfl_xor_sync(gmask, v, 1);
        v += __shfl_xor_sync(gmask, v, 2);
        if (s == 0) __stcs(po + (size_t)c * BINS, v * 0.25f);
        p += HW;
    }
}

extern "C" void kernel_launch(void* const* d_in, const int* in_sizes, int n_in,
                              void* d_out, int out_size)
{
    const float* f0   = (const float*)d_in[0];
    const float* f1   = (const float*)d_in[1];
    const float* f2   = (const float*)d_in[2];
    const float* f3   = (const float*)d_in[3];
    const float* rois = (const float*)d_in[4];
    float* out = (float*)d_out;

    const int K = in_sizes[4] / 5;
    roi_extract_kernel<<<K, BLK>>>(f0, f1, f2, f3, rois, out);
}